// round 14
// baseline (speedup 1.0000x reference)
#include <cuda_runtime.h>
#include <cuda_bf16.h>
#include <cstdint>
#include <cstddef>

#define TT 2048
#define BB 16
#define DIMK 1024
#define NN 64
#define NTOT 256
#define MROWS (TT*BB)
#define LC 16
#define NCH (TT/LC)

#if defined(__CUDA_ARCH__) && (__CUDA_ARCH__ >= 1000) && \
    (defined(__CUDA_ARCH_FEAT_SM103_ALL) || defined(__CUDA_ARCH_FEAT_SM100_ALL))
#define HAS_TC 1
#else
#define HAS_TC 0
#endif

__device__ __align__(128) __nv_bfloat16 g_whi[NTOT * DIMK];
__device__ __align__(128) __nv_bfloat16 g_wlo[NTOT * DIMK];
__device__ __align__(128) float scr_w[NTOT * DIMK];
__device__ __align__(128) float scr_raw[(size_t)MROWS * NTOT];
__device__ __align__(128) float scr_kk[(size_t)BB * NCH * 256];
__device__ __align__(128) float scr_kq[(size_t)BB * NCH * 256];
__device__ __align__(128) float scr_ivg[(size_t)MROWS * 64];   // 1/g per (m, n)

#define SWZ(off) ((off) ^ (((off) >> 3) & 0x70))

__device__ __forceinline__ void cp_async16(void *smem_dst, const void *gsrc) {
    unsigned sa = (unsigned)__cvta_generic_to_shared(smem_dst);
    asm volatile("cp.async.ca.shared.global [%0], [%1], 16;" :: "r"(sa), "l"(gsrc));
}
__device__ __forceinline__ void cp_async4(void *smem_dst, const void *gsrc) {
    unsigned sa = (unsigned)__cvta_generic_to_shared(smem_dst);
    asm volatile("cp.async.ca.shared.global [%0], [%1], 4;" :: "r"(sa), "l"(gsrc));
}
__device__ __forceinline__ unsigned long long pack2(float x, float y) {
    unsigned long long r; asm("mov.b64 %0, {%1, %2};" : "=l"(r) : "f"(x), "f"(y)); return r;
}
__device__ __forceinline__ void unpack2(unsigned long long v, float &x, float &y) {
    asm("mov.b64 {%0, %1}, %2;" : "=f"(x), "=f"(y) : "l"(v));
}
__device__ __forceinline__ void ffma2(unsigned long long &c, unsigned long long a, unsigned long long b) {
    asm("fma.rn.f32x2 %0, %1, %2, %0;" : "+l"(c) : "l"(a), "l"(b));
}
__device__ __forceinline__ void split4(float4 v, uint2 &uh, uint2 &ul) {
    __nv_bfloat16 h0 = __float2bfloat16(v.x), h1 = __float2bfloat16(v.y);
    __nv_bfloat16 h2 = __float2bfloat16(v.z), h3 = __float2bfloat16(v.w);
    __nv_bfloat16 l0 = __float2bfloat16(v.x - __bfloat162float(h0));
    __nv_bfloat16 l1 = __float2bfloat16(v.y - __bfloat162float(h1));
    __nv_bfloat16 l2 = __float2bfloat16(v.z - __bfloat162float(h2));
    __nv_bfloat16 l3 = __float2bfloat16(v.w - __bfloat162float(h3));
    uh.x = ((uint32_t)__bfloat16_as_ushort(h1) << 16) | __bfloat16_as_ushort(h0);
    uh.y = ((uint32_t)__bfloat16_as_ushort(h3) << 16) | __bfloat16_as_ushort(h2);
    ul.x = ((uint32_t)__bfloat16_as_ushort(l1) << 16) | __bfloat16_as_ushort(l0);
    ul.y = ((uint32_t)__bfloat16_as_ushort(l3) << 16) | __bfloat16_as_ushort(l2);
}

#if HAS_TC
__device__ __forceinline__ uint64_t make_desc(uint32_t a) {
    return ((uint64_t)2 << 61) | ((uint64_t)1 << 46) | ((uint64_t)64 << 32) |
           ((uint64_t)1 << 16) | ((a >> 4) & 0x3FFF);
}
__device__ __forceinline__ void mbar_init(uint32_t addr, uint32_t cnt) {
    asm volatile("mbarrier.init.shared.b64 [%0], %1;" :: "r"(addr), "r"(cnt) : "memory");
}
__device__ __forceinline__ void mbar_wait(uint32_t addr, uint32_t parity) {
    uint32_t done;
    asm volatile("{\n\t.reg .pred p;\n\t"
        "mbarrier.try_wait.parity.acquire.cta.shared::cta.b64 p, [%1], %2;\n\t"
        "selp.b32 %0, 1, 0, p;\n\t}" : "=r"(done) : "r"(addr), "r"(parity) : "memory");
    if (!done) {
        asm volatile("{\n\t.reg .pred P1;\n\t"
            "WL_%=:\n\t"
            "mbarrier.try_wait.parity.acquire.cta.shared::cta.b64 P1, [%0], %1, 0x989680;\n\t"
            "@P1 bra.uni WD_%=;\n\tbra.uni WL_%=;\n\tWD_%=:\n\t}"
            :: "r"(addr), "r"(parity) : "memory");
    }
}
__device__ __forceinline__ void mma_f16_ss(uint32_t d, uint64_t a, uint64_t b,
                                           uint32_t idesc, uint32_t en) {
    asm volatile("{\n\t.reg .pred p;\n\t"
        "setp.ne.u32 p, %5, 0;\n\t"
        "tcgen05.mma.cta_group::1.kind::f16 [%0], %1, %2, %3, {%4, %4, %4, %4}, p;\n\t}"
        :: "r"(d), "l"(a), "l"(b), "r"(idesc), "r"(0u), "r"(en) : "memory");
}
#endif

__global__ void copyw_kernel(const float *__restrict__ wk, const float *__restrict__ wv,
                             const float *__restrict__ wq, const float *__restrict__ wb) {
#if !HAS_TC
    int i = blockIdx.x * 256 + threadIdx.x;
    int sel = i >> 16, off = i & 65535;
    const float *src = (sel == 0) ? wk : (sel == 1) ? wv : (sel == 2) ? wq : wb;
    scr_w[i] = src[off];
#endif
}

__global__ void convw_kernel(const float *__restrict__ wk, const float *__restrict__ wv,
                             const float *__restrict__ wq, const float *__restrict__ wb) {
#if HAS_TC
    int g = blockIdx.x * 256 + threadIdx.x;
    int i4 = g * 4;
    int n = i4 >> 10, k = i4 & 1023;
    int sel = n >> 6, r = n & 63;
    const float *src = (sel == 0) ? wk : (sel == 1) ? wv : (sel == 2) ? wq : wb;
    float4 v = *(const float4 *)(src + (size_t)r * DIMK + k);
    uint2 uh, ul; split4(v, uh, ul);
    *(uint2 *)(g_whi + i4) = uh; *(uint2 *)(g_wlo + i4) = ul;
#endif
}

__global__ __launch_bounds__(256, 2) void fb_gemm_kernel(const float *__restrict__ X) {
#if !HAS_TC
    __shared__ __align__(16) float As[16 * 128];
    __shared__ __align__(16) float Bs[16 * 128];
    const int tid = threadIdx.x;
    const int m0 = blockIdx.x * 128, n0 = blockIdx.y * 128;
    const int tm = tid >> 4, tn = tid & 15;
    unsigned long long acc[4][8];
#pragma unroll
    for (int i = 0; i < 4; i++)
#pragma unroll
        for (int j = 0; j < 8; j++) acc[i][j] = 0ull;
    const int u0 = tid * 2;
    const int arow0 = u0 >> 2, ac40 = u0 & 3;
    const int arow1 = (u0 + 1) >> 2, ac41 = (u0 + 1) & 3;
    const float *Xb = X + (size_t)m0 * DIMK;
    const float *Wb = scr_w + (size_t)n0 * DIMK;
    for (int kt = 0; kt < DIMK; kt += 16) {
        float4 a0 = *(const float4 *)(Xb + (size_t)arow0 * DIMK + kt + ac40 * 4);
        float4 a1 = *(const float4 *)(Xb + (size_t)arow1 * DIMK + kt + ac41 * 4);
        float4 b0 = *(const float4 *)(Wb + (size_t)arow0 * DIMK + kt + ac40 * 4);
        float4 b1 = *(const float4 *)(Wb + (size_t)arow1 * DIMK + kt + ac41 * 4);
        __syncthreads();
        {
            int k0 = ac40 * 4, k1 = ac41 * 4;
            As[(k0+0)*128+arow0]=a0.x; As[(k0+1)*128+arow0]=a0.y;
            As[(k0+2)*128+arow0]=a0.z; As[(k0+3)*128+arow0]=a0.w;
            As[(k1+0)*128+arow1]=a1.x; As[(k1+1)*128+arow1]=a1.y;
            As[(k1+2)*128+arow1]=a1.z; As[(k1+3)*128+arow1]=a1.w;
            Bs[(k0+0)*128+arow0]=b0.x; Bs[(k0+1)*128+arow0]=b0.y;
            Bs[(k0+2)*128+arow0]=b0.z; Bs[(k0+3)*128+arow0]=b0.w;
            Bs[(k1+0)*128+arow1]=b1.x; Bs[(k1+1)*128+arow1]=b1.y;
            Bs[(k1+2)*128+arow1]=b1.z; Bs[(k1+3)*128+arow1]=b1.w;
        }
        __syncthreads();
#pragma unroll
        for (int k = 0; k < 16; k++) {
            const ulonglong2 *pa = (const ulonglong2 *)&As[k * 128 + tm * 8];
            ulonglong2 av0 = pa[0], av1 = pa[1];
            float4 bv0 = *(const float4 *)&Bs[k * 128 + tn * 8];
            float4 bv1 = *(const float4 *)&Bs[k * 128 + tn * 8 + 4];
            unsigned long long ap[4] = {av0.x, av0.y, av1.x, av1.y};
            unsigned long long bbx[8];
            bbx[0]=pack2(bv0.x,bv0.x); bbx[1]=pack2(bv0.y,bv0.y);
            bbx[2]=pack2(bv0.z,bv0.z); bbx[3]=pack2(bv0.w,bv0.w);
            bbx[4]=pack2(bv1.x,bv1.x); bbx[5]=pack2(bv1.y,bv1.y);
            bbx[6]=pack2(bv1.z,bv1.z); bbx[7]=pack2(bv1.w,bv1.w);
#pragma unroll
            for (int mp = 0; mp < 4; mp++)
#pragma unroll
                for (int n = 0; n < 8; n++) ffma2(acc[mp][n], ap[mp], bbx[n]);
        }
    }
#pragma unroll
    for (int mp = 0; mp < 4; mp++) {
        float lo[8], hi[8];
#pragma unroll
        for (int n = 0; n < 8; n++) unpack2(acc[mp][n], lo[n], hi[n]);
        int mA = m0 + tm * 8 + mp * 2;
        float *outp = scr_raw + (size_t)mA * NTOT + n0 + tn * 8;
        *(float4 *)(outp)            = make_float4(lo[0], lo[1], lo[2], lo[3]);
        *(float4 *)(outp + 4)        = make_float4(lo[4], lo[5], lo[6], lo[7]);
        *(float4 *)(outp + NTOT)     = make_float4(hi[0], hi[1], hi[2], hi[3]);
        *(float4 *)(outp + NTOT + 4) = make_float4(hi[4], hi[5], hi[6], hi[7]);
    }
#endif
}

// ======================================================================
// Fused tcgen05 GEMM: loads fp32 x, converts to split-bf16 in SMEM,
// 3-product MMA, and fused kn/g/ivg epilogue.
// ======================================================================
#define GK 64
#define NKC (DIMK / GK)              // 16
#define XA 16384                     // one x tile (128 rows x 128B)
#define WBY 32768                    // one w tile (256 rows x 128B)
#define ST2 (2 * XA + 2 * WBY)       // 98304 per stage
#define XSTAGE_OFF (1024 + 2 * ST2)  // fp32 staging (32768 B)
#define SMEM_GEMM_TOTAL (XSTAGE_OFF + 32768)   // 230400
#define G_IDESC ((1u << 4) | (1u << 7) | (1u << 10) | ((NTOT / 8) << 17) | ((128 / 16) << 24))

extern __shared__ __align__(1024) char gsm[];

#if HAS_TC
__device__ __forceinline__ void loadW(char *stage, int kc, int tid) {
    const char *wh = (const char *)(g_whi + kc * GK);
    const char *wl = (const char *)(g_wlo + kc * GK);
#pragma unroll
    for (int i = 0; i < 16; i++) {
        int idx = tid + i * 128;
        int row = idx >> 3, gr = idx & 7;
        uint32_t sw = SWZ(row * 128 + gr * 16);
        size_t gof = (size_t)row * (DIMK * 2) + gr * 16;
        cp_async16(stage + 2 * XA + sw, wh + gof);
        cp_async16(stage + 2 * XA + WBY + sw, wl + gof);
    }
}
__device__ __forceinline__ void loadX(const float *X, int m0, int kc, int tid) {
    char *st = gsm + XSTAGE_OFF;
#pragma unroll
    for (int i = 0; i < 16; i++) {
        int idx = tid + i * 128;
        int row = idx >> 4, f4 = idx & 15;   // 128 rows x 16 float4
        cp_async16(st + row * 256 + f4 * 16,
                   X + (size_t)(m0 + row) * DIMK + kc * GK + f4 * 4);
    }
}
__device__ __forceinline__ void convX(char *stage, int tid) {
    const float *row = (const float *)(gsm + XSTAGE_OFF) + tid * 64;
    char *hi = stage, *lo = stage + XA;
#pragma unroll
    for (int gr = 0; gr < 8; gr++) {
        float4 f0 = *(const float4 *)(row + gr * 8);
        float4 f1 = *(const float4 *)(row + gr * 8 + 4);
        uint2 h0, l0, h1, l1;
        split4(f0, h0, l0); split4(f1, h1, l1);
        uint32_t sw = SWZ(tid * 128 + gr * 16);
        *(uint4 *)(hi + sw) = make_uint4(h0.x, h0.y, h1.x, h1.y);
        *(uint4 *)(lo + sw) = make_uint4(l0.x, l0.y, l1.x, l1.y);
    }
}

#define TMEM_LD32(arr, addr) \
    asm volatile( \
        "tcgen05.ld.sync.aligned.32x32b.x32.b32 " \
        "{%0, %1, %2, %3, %4, %5, %6, %7, %8, %9, %10, %11, %12, %13, %14, %15, " \
        " %16, %17, %18, %19, %20, %21, %22, %23, %24, %25, %26, %27, %28, %29, %30, %31}, [%32];" \
        : "=r"((arr)[0]),"=r"((arr)[1]),"=r"((arr)[2]),"=r"((arr)[3]), \
          "=r"((arr)[4]),"=r"((arr)[5]),"=r"((arr)[6]),"=r"((arr)[7]), \
          "=r"((arr)[8]),"=r"((arr)[9]),"=r"((arr)[10]),"=r"((arr)[11]), \
          "=r"((arr)[12]),"=r"((arr)[13]),"=r"((arr)[14]),"=r"((arr)[15]), \
          "=r"((arr)[16]),"=r"((arr)[17]),"=r"((arr)[18]),"=r"((arr)[19]), \
          "=r"((arr)[20]),"=r"((arr)[21]),"=r"((arr)[22]),"=r"((arr)[23]), \
          "=r"((arr)[24]),"=r"((arr)[25]),"=r"((arr)[26]),"=r"((arr)[27]), \
          "=r"((arr)[28]),"=r"((arr)[29]),"=r"((arr)[30]),"=r"((arr)[31]) \
        : "r"(addr)); \
    asm volatile("tcgen05.wait::ld.sync.aligned;" ::: "memory")
#endif

__global__ __launch_bounds__(128, 1)
void mma_gemm_kernel(const float *__restrict__ X, const float *__restrict__ b_beta) {
#if HAS_TC
    const int tid = threadIdx.x, wid = tid >> 5, lid = tid & 31;
    const int m0 = blockIdx.x * 128;
    uint32_t sbase = (uint32_t)__cvta_generic_to_shared(gsm);
    if (wid == 0) {
        asm volatile("tcgen05.alloc.cta_group::1.sync.aligned.shared::cta.b32 [%0], %1;"
                     :: "r"(sbase), "r"(256u) : "memory");
        asm volatile("tcgen05.relinquish_alloc_permit.cta_group::1.sync.aligned;");
    }
    if (tid == 0) { mbar_init(sbase + 16, 1); mbar_init(sbase + 24, 1); }
    __syncthreads();
    uint32_t tmem;
    asm volatile("ld.shared.b32 %0, [%1];" : "=r"(tmem) : "r"(sbase));

    char *st0 = gsm + 1024, *st1 = gsm + 1024 + ST2;

    // prologue: G0 = {W0->s0, X0}; then W1->s1; conv X0; then X1.
    loadW(st0, 0, tid); loadX(X, m0, 0, tid);
    asm volatile("cp.async.commit_group;");
    loadW(st1, 1, tid);
    asm volatile("cp.async.commit_group;");
    asm volatile("cp.async.wait_group 1;" ::: "memory");
    __syncthreads();
    convX(st0, tid);
    __syncthreads();
    loadX(X, m0, 1, tid);
    asm volatile("cp.async.commit_group;");

    int ph0 = 0, ph1 = 0;
    for (int c = 0; c < NKC; c++) {
        const int s = c & 1;
        char *sc = (s == 0) ? st0 : st1;
        char *so = (s == 0) ? st1 : st0;
        uint32_t sa = sbase + 1024 + s * ST2;

        if (tid == 0) {
            asm volatile("fence.proxy.async.shared::cta;" ::: "memory");
            uint64_t ahi = make_desc(sa), alo = make_desc(sa + XA);
            uint64_t bhi = make_desc(sa + 2 * XA), blo = make_desc(sa + 2 * XA + WBY);
#pragma unroll
            for (int k = 0; k < 4; k++)
                mma_f16_ss(tmem, ahi + k * 2, bhi + k * 2, G_IDESC, !(c == 0 && k == 0));
#pragma unroll
            for (int k = 0; k < 4; k++)
                mma_f16_ss(tmem, ahi + k * 2, blo + k * 2, G_IDESC, 1u);
#pragma unroll
            for (int k = 0; k < 4; k++)
                mma_f16_ss(tmem, alo + k * 2, bhi + k * 2, G_IDESC, 1u);
            asm volatile(
                "tcgen05.commit.cta_group::1.mbarrier::arrive::one.shared::cluster.b64 [%0];"
                :: "r"(sbase + 16 + s * 8) : "memory");
        }
        if (c + 1 < NKC) {
            // G_{c+1} (W(c+1)->so, X(c+1)->staging) was committed earlier; land it.
            asm volatile("cp.async.wait_group 0;" ::: "memory");
            __syncthreads();
            convX(so, tid);          // stage so free: MMA(c-1) completed (waited at iter c-1)
            __syncthreads();
        }
        if (c + 2 < NKC) {
            if (s == 0) { mbar_wait(sbase + 16, ph0 & 1); ph0++; }
            else        { mbar_wait(sbase + 24, ph1 & 1); ph1++; }
            loadW(sc, c + 2, tid);   // stage sc free now (MMA(c) done)
            loadX(X, m0, c + 2, tid);
            asm volatile("cp.async.commit_group;");
        }
    }
    // drain: MMA(14) -> mbar0 phase ph0, MMA(15) -> mbar1 phase ph1
    mbar_wait(sbase + 16, ph0 & 1);
    mbar_wait(sbase + 24, ph1 & 1);
    asm volatile("tcgen05.fence::after_thread_sync;" ::: "memory");

    // ===== fused epilogue: kn normalize, raw v/q, gate g + ivg =====
    const int m = m0 + wid * 32 + lid;
    float *orow = scr_raw + (size_t)m * NTOT;
    {
        uint32_t ra[32], rb[32];
        // k: cols 0..63
        TMEM_LD32(ra, tmem + 0);
        TMEM_LD32(rb, tmem + 32);
        float ss = 0.f;
#pragma unroll
        for (int i = 0; i < 32; i++) {
            float x0 = __uint_as_float(ra[i]), x1 = __uint_as_float(rb[i]);
            ss = fmaf(x0, x0, ss); ss = fmaf(x1, x1, ss);
        }
        float inv = 1.0f / (sqrtf(ss) + 1e-6f);
        float4 *o4 = (float4 *)orow;
#pragma unroll
        for (int i = 0; i < 8; i++) {
            o4[i]     = make_float4(__uint_as_float(ra[i*4])*inv, __uint_as_float(ra[i*4+1])*inv,
                                    __uint_as_float(ra[i*4+2])*inv, __uint_as_float(ra[i*4+3])*inv);
            o4[i + 8] = make_float4(__uint_as_float(rb[i*4])*inv, __uint_as_float(rb[i*4+1])*inv,
                                    __uint_as_float(rb[i*4+2])*inv, __uint_as_float(rb[i*4+3])*inv);
        }
        // v (cols 64..127) and q (cols 128..191): raw
#pragma unroll 1
        for (int cb = 2; cb < 6; cb++) {
            TMEM_LD32(ra, tmem + cb * 32);
            float4 *p4 = (float4 *)(orow + cb * 32);
#pragma unroll
            for (int i = 0; i < 8; i++)
                p4[i] = make_float4(__uint_as_float(ra[i*4]), __uint_as_float(ra[i*4+1]),
                                    __uint_as_float(ra[i*4+2]), __uint_as_float(ra[i*4+3]));
        }
        // beta (cols 192..255): g = sigmoid(beta + b), ivg = 1 + exp(-..)
        float *ivg = scr_ivg + (size_t)m * 64;
#pragma unroll 1
        for (int cb = 6; cb < 8; cb++) {
            TMEM_LD32(ra, tmem + cb * 32);
            int base = (cb - 6) * 32;
            float gv[32];
#pragma unroll
            for (int i = 0; i < 32; i++) {
                float e = __expf(-(__uint_as_float(ra[i]) + __ldg(b_beta + base + i)));
                gv[i] = 1.0f / (1.0f + e);
                ra[i] = __float_as_uint(1.0f + e);
            }
            float4 *p4 = (float4 *)(orow + 192 + base);
            float4 *v4 = (float4 *)(ivg + base);
#pragma unroll
            for (int i = 0; i < 8; i++) {
                p4[i] = make_float4(gv[i*4], gv[i*4+1], gv[i*4+2], gv[i*4+3]);
                v4[i] = make_float4(__uint_as_float(ra[i*4]), __uint_as_float(ra[i*4+1]),
                                    __uint_as_float(ra[i*4+2]), __uint_as_float(ra[i*4+3]));
            }
        }
    }
    __syncthreads();
    if (wid == 0)
        asm volatile("tcgen05.dealloc.cta_group::1.sync.aligned.b32 %0, %1;"
                     :: "r"(tmem), "r"(256u));
#endif
}

// ===== epilogue (fallback path only; TC path fuses it into the GEMM) =====
__global__ void epilogue_kernel(const float *__restrict__ b_beta) {
#if !HAS_TC
    int warp = (blockIdx.x * blockDim.x + threadIdx.x) >> 5;
    int lane = threadIdx.x & 31;
    if (warp >= MROWS) return;
    float *row = scr_raw + (size_t)warp * NTOT;
    int i0 = lane * 2;
    float2 kv = *(float2 *)(row + i0);
    float2 bt = *(float2 *)(row + 192 + i0);
    float nk = kv.x * kv.x + kv.y * kv.y;
#pragma unroll
    for (int off = 16; off; off >>= 1) nk += __shfl_xor_sync(0xffffffffu, nk, off);
    float inv = 1.0f / (sqrtf(nk) + 1e-6f);
    float ex = __expf(-(bt.x + b_beta[i0]));
    float ey = __expf(-(bt.y + b_beta[i0 + 1]));
    *(float2 *)(row + i0)       = make_float2(kv.x * inv, kv.y * inv);
    *(float2 *)(row + 192 + i0) = make_float2(1.0f / (1.0f + ex), 1.0f / (1.0f + ey));
    *(float2 *)(scr_ivg + (size_t)warp * 64 + i0) = make_float2(1.0f + ex, 1.0f + ey);
#endif
}

// ===== gram: per (b,chunk) KK[j][t]=kn_j.kn_t, KQ[j][t]=kn_j.q_t =====
__global__ __launch_bounds__(256) void gram_kernel() {
    __shared__ __align__(16) float kn_s[16 * 68], q_s[16 * 68];
    const int gb = blockIdx.x;
    const int ch = gb >> 4, b = gb & 15;
    const int tid = threadIdx.x;
    {
        int t = tid >> 4, c4 = tid & 15;
        size_t m = (size_t)(ch * 16 + t) * BB + b;
        float4 a = *(const float4 *)(scr_raw + m * NTOT + c4 * 4);
        float4 c = *(const float4 *)(scr_raw + m * NTOT + 128 + c4 * 4);
        *(float4 *)(kn_s + t * 68 + c4 * 4) = a;
        *(float4 *)(q_s  + t * 68 + c4 * 4) = c;
    }
    __syncthreads();
    const int j = tid >> 4, t = tid & 15;
    float ak = 0.f, aq = 0.f;
#pragma unroll
    for (int c4 = 0; c4 < 16; c4++) {
        float4 a  = *(const float4 *)(kn_s + j * 68 + c4 * 4);
        float4 bk = *(const float4 *)(kn_s + t * 68 + c4 * 4);
        float4 bq = *(const float4 *)(q_s  + t * 68 + c4 * 4);
        ak = fmaf(a.x,bk.x,fmaf(a.y,bk.y,fmaf(a.z,bk.z,fmaf(a.w,bk.w,ak))));
        aq = fmaf(a.x,bq.x,fmaf(a.y,bq.y,fmaf(a.z,bq.z,fmaf(a.w,bq.w,aq))));
    }
    scr_kk[(size_t)gb * 256 + j * 16 + t] = ak;
    scr_kq[(size_t)gb * 256 + j * 16 + t] = aq;
}

// ===== WY chunked scan (unchanged from R13, passing) =====
struct __align__(16) ScanBuf {
    float kn[16 * 68], q[16 * 68];
    float v[8 * 16], g[8 * 16], ig[8 * 16];   // [row][t]
    float kk[256], kq[256];
};

__device__ __forceinline__ void wy_issue(ScanBuf *sb, int ch, int b, int r0, int tid) {
#pragma unroll
    for (int i = 0; i < 4; i++) {
        int u = tid + i * 256;
        if (u < 512) {
            int t = (u & 255) >> 4, f4 = u & 15;
            size_t m = (size_t)(ch * 16 + t) * BB + b;
            if (u < 256) cp_async16(sb->kn + t * 68 + f4 * 4, scr_raw + m * NTOT + f4 * 4);
            else         cp_async16(sb->q  + t * 68 + f4 * 4, scr_raw + m * NTOT + 128 + f4 * 4);
        } else if (u < 640) {
            int w = u - 512;
            size_t base = (size_t)(ch * 16 + b) * 256 + (w & 63) * 4;
            if (w < 64) cp_async16(sb->kk + (w & 63) * 4, scr_kk + base);
            else        cp_async16(sb->kq + (w & 63) * 4, scr_kq + base);
        } else {
            int w = u - 640;
            int arr = w >> 7, e = w & 127;
            int t = e >> 3, row = e & 7;
            size_t m = (size_t)(ch * 16 + t) * BB + b;
            float *dst = (arr == 0) ? (sb->v + row * 16 + t)
                       : (arr == 1) ? (sb->g + row * 16 + t)
                                    : (sb->ig + row * 16 + t);
            const float *src = (arr == 0) ? (scr_raw + m * NTOT + 64 + r0 + row)
                             : (arr == 1) ? (scr_raw + m * NTOT + 192 + r0 + row)
                                          : (scr_ivg + m * 64 + r0 + row);
            cp_async4(dst, src);
        }
    }
}

__global__ __launch_bounds__(256) void wy_scan_kernel(const float *__restrict__ S0,
                                                      float *__restrict__ out,
                                                      int write_sfinal) {
    __shared__ ScanBuf sb[2];
    __shared__ __align__(16) float S_s[8 * 68];
    __shared__ __align__(16) float A_s[8 * 16], Aq_s[8 * 16];
    __shared__ float cp_s[8 * 17];
    __shared__ float Gs_s[16 * 8];
    __shared__ float sh_out[16 * 8];

    const int b = blockIdx.x, r0 = blockIdx.y * 8;
    const int tid = threadIdx.x;

    if (tid < 128) {
        const int rl = tid >> 4, cc = tid & 15;
        const float *sp = S0 + ((size_t)b * 64 + r0 + rl) * 64 + cc * 4;
        *(float4 *)(S_s + rl * 68 + cc * 4) = *(const float4 *)sp;
    }

    wy_issue(&sb[0], 0, b, r0, tid);
    asm volatile("cp.async.commit_group;");

    for (int ch = 0; ch < NCH; ch++) {
        const int pb = ch & 1;
        ScanBuf *B = &sb[pb];
        if (ch + 1 < NCH) {
            wy_issue(&sb[pb ^ 1], ch + 1, b, r0, tid);
            asm volatile("cp.async.commit_group;");
            asm volatile("cp.async.wait_group 1;");
        } else {
            asm volatile("cp.async.wait_group 0;");
        }
        __syncthreads();

        {
            const int e = tid & 127;
            const int row = e >> 4, t = e & 15;
            const float *vecs = (tid < 128) ? B->kn : B->q;
            float acc0 = 0.f;
#pragma unroll
            for (int s4 = 0; s4 < 16; s4++) {
                float4 sv = *(const float4 *)(S_s + row * 68 + s4 * 4);
                float4 kv = *(const float4 *)(vecs + t * 68 + s4 * 4);
                acc0 = fmaf(sv.x,kv.x,fmaf(sv.y,kv.y,fmaf(sv.z,kv.z,fmaf(sv.w,kv.w,acc0))));
            }
            if (tid < 128) A_s [row * 16 + t] = acc0;
            else           Aq_s[row * 16 + t] = acc0;
        }
        __syncthreads();

        if (tid < 8) {
            const int row = tid;
            float a[16], vv[16], gg[16], ii[16];
#pragma unroll
            for (int s4 = 0; s4 < 4; s4++) {
                float4 t0 = *(const float4 *)(A_s   + row * 16 + s4 * 4);
                float4 t1 = *(const float4 *)(B->v  + row * 16 + s4 * 4);
                float4 t2 = *(const float4 *)(B->g  + row * 16 + s4 * 4);
                float4 t3 = *(const float4 *)(B->ig + row * 16 + s4 * 4);
                a [s4*4+0]=t0.x; a [s4*4+1]=t0.y; a [s4*4+2]=t0.z; a [s4*4+3]=t0.w;
                vv[s4*4+0]=t1.x; vv[s4*4+1]=t1.y; vv[s4*4+2]=t1.z; vv[s4*4+3]=t1.w;
                gg[s4*4+0]=t2.x; gg[s4*4+1]=t2.y; gg[s4*4+2]=t2.z; gg[s4*4+3]=t2.w;
                ii[s4*4+0]=t3.x; ii[s4*4+1]=t3.y; ii[s4*4+2]=t3.z; ii[s4*4+3]=t3.w;
            }
            float acc[16];
#pragma unroll
            for (int u = 0; u < 16; u++) acc[u] = 0.f;
            float cp[16];
            float G = 1.0f, iG = 1.0f;
#pragma unroll
            for (int t = 0; t < 16; t++) {
                float delta = vv[t] - G * (a[t] + acc[t]);
                G *= gg[t];
                iG *= ii[t];
                float ct = delta * iG;
                cp[t] = ct;
                Gs_s[t * 8 + row] = G;
#pragma unroll
                for (int u = t + 1; u < 16; u++)
                    acc[u] = fmaf(ct, B->kk[t * 16 + u], acc[u]);
            }
#pragma unroll
            for (int j = 0; j < 16; j++) cp_s[row * 17 + j] = cp[j];
        }
        __syncthreads();

        if (tid < 128) {
            const int rl = tid >> 4, cc = tid & 15;
            float gl = Gs_s[15 * 8 + rl];
            float4 s0 = *(const float4 *)(S_s + rl * 68 + cc * 4);
#pragma unroll
            for (int j = 0; j < 16; j++) {
                float cj = cp_s[rl * 17 + j];
                float4 kv = *(const float4 *)(B->kn + j * 68 + cc * 4);
                s0.x = fmaf(cj, kv.x, s0.x); s0.y = fmaf(cj, kv.y, s0.y);
                s0.z = fmaf(cj, kv.z, s0.z); s0.w = fmaf(cj, kv.w, s0.w);
            }
            s0.x *= gl; s0.y *= gl; s0.z *= gl; s0.w *= gl;
            *(float4 *)(S_s + rl * 68 + cc * 4) = s0;
        } else {
            const int e = tid - 128;
            const int row = e >> 4, t = e & 15;
            float sum = Aq_s[row * 16 + t];
            for (int j = 0; j <= t; j++)
                sum = fmaf(cp_s[row * 17 + j], B->kq[j * 16 + t], sum);
            float Sq = Gs_s[t * 8 + row] * sum;
            float sg = 1.0f / (1.0f + __expf(-Sq));
            sh_out[t * 8 + row] = Sq * Sq * sg;
        }
        __syncthreads();

        if (tid < 128) {
            const int t = tid >> 3, r = tid & 7;
            out[(size_t)(ch * 16 + t) * (BB * NN) + b * NN + r0 + r] = sh_out[t * 8 + r];
        }
    }

    if (write_sfinal && tid < 128) {
        const int rl = tid >> 4, cc = tid & 15;
        float *sf = out + (size_t)TT * BB * NN + ((size_t)b * 64 + r0 + rl) * 64 + cc * 4;
        *(float4 *)sf = *(const float4 *)(S_s + rl * 68 + cc * 4);
    }
}

// ======================================================================
extern "C" void kernel_launch(void *const *d_in, const int *in_sizes, int n_in,
                              void *d_out, int out_size) {
    const float *x  = (const float *)d_in[0];
    const float *S0 = (const float *)d_in[1];
    const float *Wk = (const float *)d_in[2];
    const float *Wv = (const float *)d_in[3];
    const float *Wq = (const float *)d_in[4];
    const float *Wb = (const float *)d_in[5];
    const float *bb = (const float *)d_in[6];
    float *out = (float *)d_out;

    cudaFuncSetAttribute(mma_gemm_kernel, cudaFuncAttributeMaxDynamicSharedMemorySize,
                         SMEM_GEMM_TOTAL);

    copyw_kernel<<<1024, 256>>>(Wk, Wv, Wq, Wb);
    convw_kernel<<<256, 256>>>(Wk, Wv, Wq, Wb);

    mma_gemm_kernel<<<MROWS / 128, 128, SMEM_GEMM_TOTAL>>>(x, bb);
    fb_gemm_kernel<<<dim3(MROWS / 128, 2), 256>>>(x);

    epilogue_kernel<<<4096, 256>>>(bb);
    gram_kernel<<<BB * NCH, 256>>>();

    int ws = (out_size >= TT * BB * NN + BB * NN * NN) ? 1 : 0;
    wy_scan_kernel<<<dim3(BB, 8), 256>>>(S0, out, ws);
}

// round 15
// speedup vs baseline: 1.0721x; 1.0721x over previous
#include <cuda_runtime.h>
#include <cuda_bf16.h>
#include <cstdint>
#include <cstddef>

#define TT 2048
#define BB 16
#define DIMK 1024
#define NN 64
#define NTOT 256
#define MROWS (TT*BB)
#define LC 16
#define NCH (TT/LC)

#if defined(__CUDA_ARCH__) && (__CUDA_ARCH__ >= 1000) && \
    (defined(__CUDA_ARCH_FEAT_SM103_ALL) || defined(__CUDA_ARCH_FEAT_SM100_ALL))
#define HAS_TC 1
#else
#define HAS_TC 0
#endif

__device__ __align__(128) __nv_bfloat16 g_xhi[(size_t)MROWS * DIMK];
__device__ __align__(128) __nv_bfloat16 g_xlo[(size_t)MROWS * DIMK];
__device__ __align__(128) __nv_bfloat16 g_whi[NTOT * DIMK];
__device__ __align__(128) __nv_bfloat16 g_wlo[NTOT * DIMK];
__device__ __align__(128) float scr_w[NTOT * DIMK];
__device__ __align__(128) float scr_raw[(size_t)MROWS * NTOT];
__device__ __align__(128) float scr_kk[(size_t)BB * NCH * 256];
__device__ __align__(128) float scr_kq[(size_t)BB * NCH * 256];
__device__ __align__(128) float scr_ivg[(size_t)MROWS * 64];   // 1/g per (m, n)

#define SWZ64(off) ((off) ^ (((off) >> 3) & 0x30))

__device__ __forceinline__ void cp_async16(void *smem_dst, const void *gsrc) {
    unsigned sa = (unsigned)__cvta_generic_to_shared(smem_dst);
    asm volatile("cp.async.ca.shared.global [%0], [%1], 16;" :: "r"(sa), "l"(gsrc));
}
__device__ __forceinline__ void cp_async4(void *smem_dst, const void *gsrc) {
    unsigned sa = (unsigned)__cvta_generic_to_shared(smem_dst);
    asm volatile("cp.async.ca.shared.global [%0], [%1], 4;" :: "r"(sa), "l"(gsrc));
}
__device__ __forceinline__ unsigned long long pack2(float x, float y) {
    unsigned long long r; asm("mov.b64 %0, {%1, %2};" : "=l"(r) : "f"(x), "f"(y)); return r;
}
__device__ __forceinline__ void unpack2(unsigned long long v, float &x, float &y) {
    asm("mov.b64 {%0, %1}, %2;" : "=f"(x), "=f"(y) : "l"(v));
}
__device__ __forceinline__ void ffma2(unsigned long long &c, unsigned long long a, unsigned long long b) {
    asm("fma.rn.f32x2 %0, %1, %2, %0;" : "+l"(c) : "l"(a), "l"(b));
}
__device__ __forceinline__ void split4(float4 v, uint2 &uh, uint2 &ul) {
    __nv_bfloat16 h0 = __float2bfloat16(v.x), h1 = __float2bfloat16(v.y);
    __nv_bfloat16 h2 = __float2bfloat16(v.z), h3 = __float2bfloat16(v.w);
    __nv_bfloat16 l0 = __float2bfloat16(v.x - __bfloat162float(h0));
    __nv_bfloat16 l1 = __float2bfloat16(v.y - __bfloat162float(h1));
    __nv_bfloat16 l2 = __float2bfloat16(v.z - __bfloat162float(h2));
    __nv_bfloat16 l3 = __float2bfloat16(v.w - __bfloat162float(h3));
    uh.x = ((uint32_t)__bfloat16_as_ushort(h1) << 16) | __bfloat16_as_ushort(h0);
    uh.y = ((uint32_t)__bfloat16_as_ushort(h3) << 16) | __bfloat16_as_ushort(h2);
    ul.x = ((uint32_t)__bfloat16_as_ushort(l1) << 16) | __bfloat16_as_ushort(l0);
    ul.y = ((uint32_t)__bfloat16_as_ushort(l3) << 16) | __bfloat16_as_ushort(l2);
}

#if HAS_TC
__device__ __forceinline__ uint64_t make_desc64(uint32_t a) {
    // SW64: layout_type=4, version=1 (Blackwell), SBO=32 (512B atom stride), LBO=1
    return ((uint64_t)4 << 61) | ((uint64_t)1 << 46) | ((uint64_t)32 << 32) |
           ((uint64_t)1 << 16) | ((a >> 4) & 0x3FFF);
}
__device__ __forceinline__ void mbar_init(uint32_t addr, uint32_t cnt) {
    asm volatile("mbarrier.init.shared.b64 [%0], %1;" :: "r"(addr), "r"(cnt) : "memory");
}
__device__ __forceinline__ void mbar_wait(uint32_t addr, uint32_t parity) {
    uint32_t done;
    asm volatile("{\n\t.reg .pred p;\n\t"
        "mbarrier.try_wait.parity.acquire.cta.shared::cta.b64 p, [%1], %2;\n\t"
        "selp.b32 %0, 1, 0, p;\n\t}" : "=r"(done) : "r"(addr), "r"(parity) : "memory");
    if (!done) {
        asm volatile("{\n\t.reg .pred P1;\n\t"
            "WL_%=:\n\t"
            "mbarrier.try_wait.parity.acquire.cta.shared::cta.b64 P1, [%0], %1, 0x989680;\n\t"
            "@P1 bra.uni WD_%=;\n\tbra.uni WL_%=;\n\tWD_%=:\n\t}"
            :: "r"(addr), "r"(parity) : "memory");
    }
}
__device__ __forceinline__ void mma_f16_ss(uint32_t d, uint64_t a, uint64_t b,
                                           uint32_t idesc, uint32_t en) {
    asm volatile("{\n\t.reg .pred p;\n\t"
        "setp.ne.u32 p, %5, 0;\n\t"
        "tcgen05.mma.cta_group::1.kind::f16 [%0], %1, %2, %3, {%4, %4, %4, %4}, p;\n\t}"
        :: "r"(d), "l"(a), "l"(b), "r"(idesc), "r"(0u), "r"(en) : "memory");
}
#endif

__global__ void copyw_kernel(const float *__restrict__ wk, const float *__restrict__ wv,
                             const float *__restrict__ wq, const float *__restrict__ wb) {
#if !HAS_TC
    int i = blockIdx.x * 256 + threadIdx.x;
    int sel = i >> 16, off = i & 65535;
    const float *src = (sel == 0) ? wk : (sel == 1) ? wv : (sel == 2) ? wq : wb;
    scr_w[i] = src[off];
#endif
}

__global__ void convw_kernel(const float *__restrict__ wk, const float *__restrict__ wv,
                             const float *__restrict__ wq, const float *__restrict__ wb) {
#if HAS_TC
    int g = blockIdx.x * 256 + threadIdx.x;
    int i4 = g * 4;
    int n = i4 >> 10, k = i4 & 1023;
    int sel = n >> 6, r = n & 63;
    const float *src = (sel == 0) ? wk : (sel == 1) ? wv : (sel == 2) ? wq : wb;
    float4 v = *(const float4 *)(src + (size_t)r * DIMK + k);
    uint2 uh, ul; split4(v, uh, ul);
    *(uint2 *)(g_whi + i4) = uh; *(uint2 *)(g_wlo + i4) = ul;
#endif
}

__global__ void convx_kernel(const float *__restrict__ x) {
#if HAS_TC
    size_t i4 = ((size_t)blockIdx.x * 256 + threadIdx.x) * 4;
    float4 v = *(const float4 *)(x + i4);
    uint2 uh, ul; split4(v, uh, ul);
    *(uint2 *)(g_xhi + i4) = uh; *(uint2 *)(g_xlo + i4) = ul;
#endif
}

__global__ __launch_bounds__(256, 2) void fb_gemm_kernel(const float *__restrict__ X) {
#if !HAS_TC
    __shared__ __align__(16) float As[16 * 128];
    __shared__ __align__(16) float Bs[16 * 128];
    const int tid = threadIdx.x;
    const int m0 = blockIdx.x * 128, n0 = blockIdx.y * 128;
    const int tm = tid >> 4, tn = tid & 15;
    unsigned long long acc[4][8];
#pragma unroll
    for (int i = 0; i < 4; i++)
#pragma unroll
        for (int j = 0; j < 8; j++) acc[i][j] = 0ull;
    const int u0 = tid * 2;
    const int arow0 = u0 >> 2, ac40 = u0 & 3;
    const int arow1 = (u0 + 1) >> 2, ac41 = (u0 + 1) & 3;
    const float *Xb = X + (size_t)m0 * DIMK;
    const float *Wb = scr_w + (size_t)n0 * DIMK;
    for (int kt = 0; kt < DIMK; kt += 16) {
        float4 a0 = *(const float4 *)(Xb + (size_t)arow0 * DIMK + kt + ac40 * 4);
        float4 a1 = *(const float4 *)(Xb + (size_t)arow1 * DIMK + kt + ac41 * 4);
        float4 b0 = *(const float4 *)(Wb + (size_t)arow0 * DIMK + kt + ac40 * 4);
        float4 b1 = *(const float4 *)(Wb + (size_t)arow1 * DIMK + kt + ac41 * 4);
        __syncthreads();
        {
            int k0 = ac40 * 4, k1 = ac41 * 4;
            As[(k0+0)*128+arow0]=a0.x; As[(k0+1)*128+arow0]=a0.y;
            As[(k0+2)*128+arow0]=a0.z; As[(k0+3)*128+arow0]=a0.w;
            As[(k1+0)*128+arow1]=a1.x; As[(k1+1)*128+arow1]=a1.y;
            As[(k1+2)*128+arow1]=a1.z; As[(k1+3)*128+arow1]=a1.w;
            Bs[(k0+0)*128+arow0]=b0.x; Bs[(k0+1)*128+arow0]=b0.y;
            Bs[(k0+2)*128+arow0]=b0.z; Bs[(k0+3)*128+arow0]=b0.w;
            Bs[(k1+0)*128+arow1]=b1.x; Bs[(k1+1)*128+arow1]=b1.y;
            Bs[(k1+2)*128+arow1]=b1.z; Bs[(k1+3)*128+arow1]=b1.w;
        }
        __syncthreads();
#pragma unroll
        for (int k = 0; k < 16; k++) {
            const ulonglong2 *pa = (const ulonglong2 *)&As[k * 128 + tm * 8];
            ulonglong2 av0 = pa[0], av1 = pa[1];
            float4 bv0 = *(const float4 *)&Bs[k * 128 + tn * 8];
            float4 bv1 = *(const float4 *)&Bs[k * 128 + tn * 8 + 4];
            unsigned long long ap[4] = {av0.x, av0.y, av1.x, av1.y};
            unsigned long long bbx[8];
            bbx[0]=pack2(bv0.x,bv0.x); bbx[1]=pack2(bv0.y,bv0.y);
            bbx[2]=pack2(bv0.z,bv0.z); bbx[3]=pack2(bv0.w,bv0.w);
            bbx[4]=pack2(bv1.x,bv1.x); bbx[5]=pack2(bv1.y,bv1.y);
            bbx[6]=pack2(bv1.z,bv1.z); bbx[7]=pack2(bv1.w,bv1.w);
#pragma unroll
            for (int mp = 0; mp < 4; mp++)
#pragma unroll
                for (int n = 0; n < 8; n++) ffma2(acc[mp][n], ap[mp], bbx[n]);
        }
    }
#pragma unroll
    for (int mp = 0; mp < 4; mp++) {
        float lo[8], hi[8];
#pragma unroll
        for (int n = 0; n < 8; n++) unpack2(acc[mp][n], lo[n], hi[n]);
        int mA = m0 + tm * 8 + mp * 2;
        float *outp = scr_raw + (size_t)mA * NTOT + n0 + tn * 8;
        *(float4 *)(outp)            = make_float4(lo[0], lo[1], lo[2], lo[3]);
        *(float4 *)(outp + 4)        = make_float4(lo[4], lo[5], lo[6], lo[7]);
        *(float4 *)(outp + NTOT)     = make_float4(hi[0], hi[1], hi[2], hi[3]);
        *(float4 *)(outp + NTOT + 4) = make_float4(hi[4], hi[5], hi[6], hi[7]);
    }
#endif
}

// ======================================================================
// tcgen05 GEMM, M-tile 256 (one wave), GK=32 chunks, SW64 swizzle,
// two M=128 accumulators (TMEM cols 0..255 and 256..511), fused epilogue.
// ======================================================================
#define GK2 32
#define NKC2 (DIMK / GK2)          // 32
#define XTB 16384                  // one 256-row x 64B tile
#define STG (4 * XTB)              // Xhi|Xlo|Whi|Wlo = 64 KB per stage
#define SMEM_MMA_TOTAL (1024 + 2 * STG)   // 132 KB
#define G_IDESC ((1u << 4) | (1u << 7) | (1u << 10) | ((NTOT / 8) << 17) | ((128 / 16) << 24))

extern __shared__ __align__(1024) char gsm[];

#if HAS_TC
__device__ __forceinline__ void load_chunk2(char *stage, int m0, int kc, int tid) {
    const char *xh = (const char *)g_xhi;
    const char *xl = (const char *)g_xlo;
    const char *wh = (const char *)g_whi;
    const char *wl = (const char *)g_wlo;
#pragma unroll
    for (int i = 0; i < 8; i++) {
        int idx = tid + i * 128;            // 0..1023
        int row = idx >> 2, gr = idx & 3;   // 256 rows x 4 x 16B groups
        uint32_t sw = SWZ64(row * 64 + gr * 16);
        size_t xoff = (size_t)(m0 + row) * (DIMK * 2) + kc * 64 + gr * 16;
        size_t woff = (size_t)row * (DIMK * 2) + kc * 64 + gr * 16;
        cp_async16(stage + sw,           xh + xoff);
        cp_async16(stage + XTB + sw,     xl + xoff);
        cp_async16(stage + 2 * XTB + sw, wh + woff);
        cp_async16(stage + 3 * XTB + sw, wl + woff);
    }
}

#define TMEM_LD32(arr, addr) \
    asm volatile( \
        "tcgen05.ld.sync.aligned.32x32b.x32.b32 " \
        "{%0, %1, %2, %3, %4, %5, %6, %7, %8, %9, %10, %11, %12, %13, %14, %15, " \
        " %16, %17, %18, %19, %20, %21, %22, %23, %24, %25, %26, %27, %28, %29, %30, %31}, [%32];" \
        : "=r"((arr)[0]),"=r"((arr)[1]),"=r"((arr)[2]),"=r"((arr)[3]), \
          "=r"((arr)[4]),"=r"((arr)[5]),"=r"((arr)[6]),"=r"((arr)[7]), \
          "=r"((arr)[8]),"=r"((arr)[9]),"=r"((arr)[10]),"=r"((arr)[11]), \
          "=r"((arr)[12]),"=r"((arr)[13]),"=r"((arr)[14]),"=r"((arr)[15]), \
          "=r"((arr)[16]),"=r"((arr)[17]),"=r"((arr)[18]),"=r"((arr)[19]), \
          "=r"((arr)[20]),"=r"((arr)[21]),"=r"((arr)[22]),"=r"((arr)[23]), \
          "=r"((arr)[24]),"=r"((arr)[25]),"=r"((arr)[26]),"=r"((arr)[27]), \
          "=r"((arr)[28]),"=r"((arr)[29]),"=r"((arr)[30]),"=r"((arr)[31]) \
        : "r"(addr)); \
    asm volatile("tcgen05.wait::ld.sync.aligned;" ::: "memory")
#endif

__global__ __launch_bounds__(128, 1)
void mma_gemm_kernel(const float *__restrict__ b_beta) {
#if HAS_TC
    const int tid = threadIdx.x, wid = tid >> 5, lid = tid & 31;
    const int m0 = blockIdx.x * 256;
    uint32_t sbase = (uint32_t)__cvta_generic_to_shared(gsm);
    if (wid == 0) {
        asm volatile("tcgen05.alloc.cta_group::1.sync.aligned.shared::cta.b32 [%0], %1;"
                     :: "r"(sbase), "r"(512u) : "memory");
        asm volatile("tcgen05.relinquish_alloc_permit.cta_group::1.sync.aligned;");
    }
    if (tid == 0) { mbar_init(sbase + 16, 1); mbar_init(sbase + 24, 1); }
    __syncthreads();
    uint32_t tmem;
    asm volatile("ld.shared.b32 %0, [%1];" : "=r"(tmem) : "r"(sbase));

    char *st0 = gsm + 1024, *st1 = gsm + 1024 + STG;
    load_chunk2(st0, m0, 0, tid);
    asm volatile("cp.async.commit_group;");
    load_chunk2(st1, m0, 1, tid);
    asm volatile("cp.async.commit_group;");

    int ph0 = 0, ph1 = 0;
    for (int c = 0; c < NKC2; c++) {
        const int s = c & 1;
        char *stp = (s == 0) ? st0 : st1;
        uint32_t sa = sbase + 1024 + s * STG;
        if (c < NKC2 - 1) asm volatile("cp.async.wait_group 1;" ::: "memory");
        else              asm volatile("cp.async.wait_group 0;" ::: "memory");
        __syncthreads();

        if (tid == 0) {
            asm volatile("fence.proxy.async.shared::cta;" ::: "memory");
            uint64_t ax0 = make_desc64(sa);
            uint64_t ax1 = make_desc64(sa + XTB);
            uint64_t aw0 = make_desc64(sa + 2 * XTB);
            uint64_t aw1 = make_desc64(sa + 3 * XTB);
#pragma unroll
            for (int h = 0; h < 2; h++) {
                uint32_t d = tmem + h * 256;
                uint64_t ho = (uint64_t)(h * 512);   // 128 rows x 64B = 8192B = 512 x 16B
#pragma unroll
                for (int k = 0; k < 2; k++)
                    mma_f16_ss(d, ax0 + ho + k * 2, aw0 + k * 2, G_IDESC, !(c == 0 && k == 0));
#pragma unroll
                for (int k = 0; k < 2; k++)
                    mma_f16_ss(d, ax0 + ho + k * 2, aw1 + k * 2, G_IDESC, 1u);
#pragma unroll
                for (int k = 0; k < 2; k++)
                    mma_f16_ss(d, ax1 + ho + k * 2, aw0 + k * 2, G_IDESC, 1u);
            }
            asm volatile(
                "tcgen05.commit.cta_group::1.mbarrier::arrive::one.shared::cluster.b64 [%0];"
                :: "r"(sbase + 16 + s * 8) : "memory");
        }
        if (c + 2 < NKC2) {
            if (s == 0) { mbar_wait(sbase + 16, ph0 & 1); ph0++; }
            else        { mbar_wait(sbase + 24, ph1 & 1); ph1++; }
            load_chunk2(stp, m0, c + 2, tid);
            asm volatile("cp.async.commit_group;");
        }
    }
    mbar_wait(sbase + 16, ph0 & 1);
    mbar_wait(sbase + 24, ph1 & 1);
    asm volatile("tcgen05.fence::after_thread_sync;" ::: "memory");

    // ===== fused epilogue over both M-halves =====
#pragma unroll 1
    for (int h = 0; h < 2; h++) {
        const uint32_t tb = tmem + h * 256;
        const int m = m0 + h * 128 + wid * 32 + lid;
        float *orow = scr_raw + (size_t)m * NTOT;
        uint32_t ra[32], rb[32];
        // k: cols 0..63 -> normalize
        TMEM_LD32(ra, tb + 0);
        TMEM_LD32(rb, tb + 32);
        float ss = 0.f;
#pragma unroll
        for (int i = 0; i < 32; i++) {
            float x0 = __uint_as_float(ra[i]), x1 = __uint_as_float(rb[i]);
            ss = fmaf(x0, x0, ss); ss = fmaf(x1, x1, ss);
        }
        float inv = 1.0f / (sqrtf(ss) + 1e-6f);
        float4 *o4 = (float4 *)orow;
#pragma unroll
        for (int i = 0; i < 8; i++) {
            o4[i]     = make_float4(__uint_as_float(ra[i*4])*inv, __uint_as_float(ra[i*4+1])*inv,
                                    __uint_as_float(ra[i*4+2])*inv, __uint_as_float(ra[i*4+3])*inv);
            o4[i + 8] = make_float4(__uint_as_float(rb[i*4])*inv, __uint_as_float(rb[i*4+1])*inv,
                                    __uint_as_float(rb[i*4+2])*inv, __uint_as_float(rb[i*4+3])*inv);
        }
        // v (cols 64..127), q (cols 128..191): raw
#pragma unroll 1
        for (int cb = 2; cb < 6; cb++) {
            TMEM_LD32(ra, tb + cb * 32);
            float4 *p4 = (float4 *)(orow + cb * 32);
#pragma unroll
            for (int i = 0; i < 8; i++)
                p4[i] = make_float4(__uint_as_float(ra[i*4]), __uint_as_float(ra[i*4+1]),
                                    __uint_as_float(ra[i*4+2]), __uint_as_float(ra[i*4+3]));
        }
        // beta (cols 192..255): g = sigmoid(beta+b), ivg = 1+exp(-..)
        float *ivg = scr_ivg + (size_t)m * 64;
#pragma unroll 1
        for (int cb = 6; cb < 8; cb++) {
            TMEM_LD32(ra, tb + cb * 32);
            int base = (cb - 6) * 32;
            float gv[32];
#pragma unroll
            for (int i = 0; i < 32; i++) {
                float e = __expf(-(__uint_as_float(ra[i]) + __ldg(b_beta + base + i)));
                gv[i] = 1.0f / (1.0f + e);
                ra[i] = __float_as_uint(1.0f + e);
            }
            float4 *p4 = (float4 *)(orow + 192 + base);
            float4 *v4 = (float4 *)(ivg + base);
#pragma unroll
            for (int i = 0; i < 8; i++) {
                p4[i] = make_float4(gv[i*4], gv[i*4+1], gv[i*4+2], gv[i*4+3]);
                v4[i] = make_float4(__uint_as_float(ra[i*4]), __uint_as_float(ra[i*4+1]),
                                    __uint_as_float(ra[i*4+2]), __uint_as_float(ra[i*4+3]));
            }
        }
    }
    __syncthreads();
    if (wid == 0)
        asm volatile("tcgen05.dealloc.cta_group::1.sync.aligned.b32 %0, %1;"
                     :: "r"(tmem), "r"(512u));
#endif
}

// ===== epilogue (fallback path only) =====
__global__ void epilogue_kernel(const float *__restrict__ b_beta) {
#if !HAS_TC
    int warp = (blockIdx.x * blockDim.x + threadIdx.x) >> 5;
    int lane = threadIdx.x & 31;
    if (warp >= MROWS) return;
    float *row = scr_raw + (size_t)warp * NTOT;
    int i0 = lane * 2;
    float2 kv = *(float2 *)(row + i0);
    float2 bt = *(float2 *)(row + 192 + i0);
    float nk = kv.x * kv.x + kv.y * kv.y;
#pragma unroll
    for (int off = 16; off; off >>= 1) nk += __shfl_xor_sync(0xffffffffu, nk, off);
    float inv = 1.0f / (sqrtf(nk) + 1e-6f);
    float ex = __expf(-(bt.x + b_beta[i0]));
    float ey = __expf(-(bt.y + b_beta[i0 + 1]));
    *(float2 *)(row + i0)       = make_float2(kv.x * inv, kv.y * inv);
    *(float2 *)(row + 192 + i0) = make_float2(1.0f / (1.0f + ex), 1.0f / (1.0f + ey));
    *(float2 *)(scr_ivg + (size_t)warp * 64 + i0) = make_float2(1.0f + ex, 1.0f + ey);
#endif
}

// ===== gram: per (b,chunk) KK[j][t]=kn_j.kn_t, KQ[j][t]=kn_j.q_t =====
__global__ __launch_bounds__(256) void gram_kernel() {
    __shared__ __align__(16) float kn_s[16 * 68], q_s[16 * 68];
    const int gb = blockIdx.x;
    const int ch = gb >> 4, b = gb & 15;
    const int tid = threadIdx.x;
    {
        int t = tid >> 4, c4 = tid & 15;
        size_t m = (size_t)(ch * 16 + t) * BB + b;
        float4 a = *(const float4 *)(scr_raw + m * NTOT + c4 * 4);
        float4 c = *(const float4 *)(scr_raw + m * NTOT + 128 + c4 * 4);
        *(float4 *)(kn_s + t * 68 + c4 * 4) = a;
        *(float4 *)(q_s  + t * 68 + c4 * 4) = c;
    }
    __syncthreads();
    const int j = tid >> 4, t = tid & 15;
    float ak = 0.f, aq = 0.f;
#pragma unroll
    for (int c4 = 0; c4 < 16; c4++) {
        float4 a  = *(const float4 *)(kn_s + j * 68 + c4 * 4);
        float4 bk = *(const float4 *)(kn_s + t * 68 + c4 * 4);
        float4 bq = *(const float4 *)(q_s  + t * 68 + c4 * 4);
        ak = fmaf(a.x,bk.x,fmaf(a.y,bk.y,fmaf(a.z,bk.z,fmaf(a.w,bk.w,ak))));
        aq = fmaf(a.x,bq.x,fmaf(a.y,bq.y,fmaf(a.z,bq.z,fmaf(a.w,bq.w,aq))));
    }
    scr_kk[(size_t)gb * 256 + j * 16 + t] = ak;
    scr_kq[(size_t)gb * 256 + j * 16 + t] = aq;
}

// ===== WY chunked scan (R13 version, passing) =====
struct __align__(16) ScanBuf {
    float kn[16 * 68], q[16 * 68];
    float v[8 * 16], g[8 * 16], ig[8 * 16];   // [row][t]
    float kk[256], kq[256];
};

__device__ __forceinline__ void wy_issue(ScanBuf *sb, int ch, int b, int r0, int tid) {
#pragma unroll
    for (int i = 0; i < 4; i++) {
        int u = tid + i * 256;
        if (u < 512) {
            int t = (u & 255) >> 4, f4 = u & 15;
            size_t m = (size_t)(ch * 16 + t) * BB + b;
            if (u < 256) cp_async16(sb->kn + t * 68 + f4 * 4, scr_raw + m * NTOT + f4 * 4);
            else         cp_async16(sb->q  + t * 68 + f4 * 4, scr_raw + m * NTOT + 128 + f4 * 4);
        } else if (u < 640) {
            int w = u - 512;
            size_t base = (size_t)(ch * 16 + b) * 256 + (w & 63) * 4;
            if (w < 64) cp_async16(sb->kk + (w & 63) * 4, scr_kk + base);
            else        cp_async16(sb->kq + (w & 63) * 4, scr_kq + base);
        } else {
            int w = u - 640;
            int arr = w >> 7, e = w & 127;
            int t = e >> 3, row = e & 7;
            size_t m = (size_t)(ch * 16 + t) * BB + b;
            float *dst = (arr == 0) ? (sb->v + row * 16 + t)
                       : (arr == 1) ? (sb->g + row * 16 + t)
                                    : (sb->ig + row * 16 + t);
            const float *src = (arr == 0) ? (scr_raw + m * NTOT + 64 + r0 + row)
                             : (arr == 1) ? (scr_raw + m * NTOT + 192 + r0 + row)
                                          : (scr_ivg + m * 64 + r0 + row);
            cp_async4(dst, src);
        }
    }
}

__global__ __launch_bounds__(256) void wy_scan_kernel(const float *__restrict__ S0,
                                                      float *__restrict__ out,
                                                      int write_sfinal) {
    __shared__ ScanBuf sb[2];
    __shared__ __align__(16) float S_s[8 * 68];
    __shared__ __align__(16) float A_s[8 * 16], Aq_s[8 * 16];
    __shared__ float cp_s[8 * 17];
    __shared__ float Gs_s[16 * 8];
    __shared__ float sh_out[16 * 8];

    const int b = blockIdx.x, r0 = blockIdx.y * 8;
    const int tid = threadIdx.x;

    if (tid < 128) {
        const int rl = tid >> 4, cc = tid & 15;
        const float *sp = S0 + ((size_t)b * 64 + r0 + rl) * 64 + cc * 4;
        *(float4 *)(S_s + rl * 68 + cc * 4) = *(const float4 *)sp;
    }

    wy_issue(&sb[0], 0, b, r0, tid);
    asm volatile("cp.async.commit_group;");

    for (int ch = 0; ch < NCH; ch++) {
        const int pb = ch & 1;
        ScanBuf *B = &sb[pb];
        if (ch + 1 < NCH) {
            wy_issue(&sb[pb ^ 1], ch + 1, b, r0, tid);
            asm volatile("cp.async.commit_group;");
            asm volatile("cp.async.wait_group 1;");
        } else {
            asm volatile("cp.async.wait_group 0;");
        }
        __syncthreads();

        {
            const int e = tid & 127;
            const int row = e >> 4, t = e & 15;
            const float *vecs = (tid < 128) ? B->kn : B->q;
            float acc0 = 0.f;
#pragma unroll
            for (int s4 = 0; s4 < 16; s4++) {
                float4 sv = *(const float4 *)(S_s + row * 68 + s4 * 4);
                float4 kv = *(const float4 *)(vecs + t * 68 + s4 * 4);
                acc0 = fmaf(sv.x,kv.x,fmaf(sv.y,kv.y,fmaf(sv.z,kv.z,fmaf(sv.w,kv.w,acc0))));
            }
            if (tid < 128) A_s [row * 16 + t] = acc0;
            else           Aq_s[row * 16 + t] = acc0;
        }
        __syncthreads();

        if (tid < 8) {
            const int row = tid;
            float a[16], vv[16], gg[16], ii[16];
#pragma unroll
            for (int s4 = 0; s4 < 4; s4++) {
                float4 t0 = *(const float4 *)(A_s   + row * 16 + s4 * 4);
                float4 t1 = *(const float4 *)(B->v  + row * 16 + s4 * 4);
                float4 t2 = *(const float4 *)(B->g  + row * 16 + s4 * 4);
                float4 t3 = *(const float4 *)(B->ig + row * 16 + s4 * 4);
                a [s4*4+0]=t0.x; a [s4*4+1]=t0.y; a [s4*4+2]=t0.z; a [s4*4+3]=t0.w;
                vv[s4*4+0]=t1.x; vv[s4*4+1]=t1.y; vv[s4*4+2]=t1.z; vv[s4*4+3]=t1.w;
                gg[s4*4+0]=t2.x; gg[s4*4+1]=t2.y; gg[s4*4+2]=t2.z; gg[s4*4+3]=t2.w;
                ii[s4*4+0]=t3.x; ii[s4*4+1]=t3.y; ii[s4*4+2]=t3.z; ii[s4*4+3]=t3.w;
            }
            float acc[16];
#pragma unroll
            for (int u = 0; u < 16; u++) acc[u] = 0.f;
            float cp[16];
            float G = 1.0f, iG = 1.0f;
#pragma unroll
            for (int t = 0; t < 16; t++) {
                float delta = vv[t] - G * (a[t] + acc[t]);
                G *= gg[t];
                iG *= ii[t];
                float ct = delta * iG;
                cp[t] = ct;
                Gs_s[t * 8 + row] = G;
#pragma unroll
                for (int u = t + 1; u < 16; u++)
                    acc[u] = fmaf(ct, B->kk[t * 16 + u], acc[u]);
            }
#pragma unroll
            for (int j = 0; j < 16; j++) cp_s[row * 17 + j] = cp[j];
        }
        __syncthreads();

        if (tid < 128) {
            const int rl = tid >> 4, cc = tid & 15;
            float gl = Gs_s[15 * 8 + rl];
            float4 s0 = *(const float4 *)(S_s + rl * 68 + cc * 4);
#pragma unroll
            for (int j = 0; j < 16; j++) {
                float cj = cp_s[rl * 17 + j];
                float4 kv = *(const float4 *)(B->kn + j * 68 + cc * 4);
                s0.x = fmaf(cj, kv.x, s0.x); s0.y = fmaf(cj, kv.y, s0.y);
                s0.z = fmaf(cj, kv.z, s0.z); s0.w = fmaf(cj, kv.w, s0.w);
            }
            s0.x *= gl; s0.y *= gl; s0.z *= gl; s0.w *= gl;
            *(float4 *)(S_s + rl * 68 + cc * 4) = s0;
        } else {
            const int e = tid - 128;
            const int row = e >> 4, t = e & 15;
            float sum = Aq_s[row * 16 + t];
            for (int j = 0; j <= t; j++)
                sum = fmaf(cp_s[row * 17 + j], B->kq[j * 16 + t], sum);
            float Sq = Gs_s[t * 8 + row] * sum;
            float sg = 1.0f / (1.0f + __expf(-Sq));
            sh_out[t * 8 + row] = Sq * Sq * sg;
        }
        __syncthreads();

        if (tid < 128) {
            const int t = tid >> 3, r = tid & 7;
            out[(size_t)(ch * 16 + t) * (BB * NN) + b * NN + r0 + r] = sh_out[t * 8 + r];
        }
    }

    if (write_sfinal && tid < 128) {
        const int rl = tid >> 4, cc = tid & 15;
        float *sf = out + (size_t)TT * BB * NN + ((size_t)b * 64 + r0 + rl) * 64 + cc * 4;
        *(float4 *)sf = *(const float4 *)(S_s + rl * 68 + cc * 4);
    }
}

// ======================================================================
extern "C" void kernel_launch(void *const *d_in, const int *in_sizes, int n_in,
                              void *d_out, int out_size) {
    const float *x  = (const float *)d_in[0];
    const float *S0 = (const float *)d_in[1];
    const float *Wk = (const float *)d_in[2];
    const float *Wv = (const float *)d_in[3];
    const float *Wq = (const float *)d_in[4];
    const float *Wb = (const float *)d_in[5];
    const float *bb = (const float *)d_in[6];
    float *out = (float *)d_out;

    cudaFuncSetAttribute(mma_gemm_kernel, cudaFuncAttributeMaxDynamicSharedMemorySize,
                         SMEM_MMA_TOTAL);

    copyw_kernel<<<1024, 256>>>(Wk, Wv, Wq, Wb);
    convw_kernel<<<256, 256>>>(Wk, Wv, Wq, Wb);
    convx_kernel<<<32768, 256>>>(x);

    mma_gemm_kernel<<<MROWS / 256, 128, SMEM_MMA_TOTAL>>>(bb);
    fb_gemm_kernel<<<dim3(MROWS / 128, 2), 256>>>(x);

    epilogue_kernel<<<4096, 256>>>(bb);
    gram_kernel<<<BB * NCH, 256>>>();

    int ws = (out_size >= TT * BB * NN + BB * NN * NN) ? 1 : 0;
    wy_scan_kernel<<<dim3(BB, 8), 256>>>(S0, out, ws);
}